// round 4
// baseline (speedup 1.0000x reference)
#include <cuda_runtime.h>
#include <cstdint>

// Masked per-graph mean pooling.
// Inputs (metadata order):
//   d_in[0]: node_embeddings float32 [B*N, D] = [4096*64, 256]
//   d_in[1]: op_idx          int32   [B, N]   = [4096, 64]
// Output: float32 [B, D] = [4096, 256]
//
// out[b, :] = sum_{n: op[b,n]!=5} h[b,n,:] / max(count, 1)
//
// Shape: 256 threads / CTA, 4 graphs / CTA.
//   tid >> 6  = local graph g (0..3)
//   tid & 63  = float4 column (0..63)
// Each thread privately accumulates its column over all 64 rows of its graph:
// no cross-thread reduction, 64 independent float4 loads in flight per thread.
// Grid = B/4 = 1024 CTAs -> single wave on 148 SMs (no wave quantization).

#define SKIP_OP 5
#define NNODES  64
#define DIM     256
#define DIM4    (DIM / 4)     // 64 float4 per row
#define GPB     4             // graphs per block

__global__ __launch_bounds__(256, 8)
void readout_kernel(const float* __restrict__ h,
                    const int* __restrict__ op,
                    float* __restrict__ out,
                    int B)
{
    const int tid  = threadIdx.x;
    const int base = blockIdx.x * GPB;          // first graph of this CTA
    const int g    = tid >> 6;                  // local graph 0..3
    const int col  = tid & (DIM4 - 1);          // float4 column 0..63
    const int gb   = base + g;                  // global graph id

    __shared__ float mask[GPB][NNODES];
    __shared__ float invcnt[GPB];

    // Stage masks: one op value per thread (4 graphs x 64 nodes = 256).
    {
        const int gi = base + (tid >> 6);
        const int ni = tid & (NNODES - 1);
        float m = 0.0f;
        if (gi < B) m = (op[(size_t)gi * NNODES + ni] != SKIP_OP) ? 1.0f : 0.0f;
        mask[tid >> 6][ni] = m;
    }
    __syncthreads();

    // Per-graph inverse count (4 threads).
    if (tid < GPB) {
        float cnt = 0.f;
#pragma unroll
        for (int r = 0; r < NNODES; r++) cnt += mask[tid][r];
        invcnt[tid] = 1.0f / fmaxf(cnt, 1.0f);
    }
    __syncthreads();

    if (gb >= B) return;

    const float4* hp = reinterpret_cast<const float4*>(
        h + (size_t)gb * NNODES * DIM);

    float4 acc = make_float4(0.f, 0.f, 0.f, 0.f);

#pragma unroll 16
    for (int r = 0; r < NNODES; r++) {
        const float  m = mask[g][r];
        const float4 v = hp[r * DIM4 + col];
        acc.x = fmaf(m, v.x, acc.x);
        acc.y = fmaf(m, v.y, acc.y);
        acc.z = fmaf(m, v.z, acc.z);
        acc.w = fmaf(m, v.w, acc.w);
    }

    const float inv = invcnt[g];
    acc.x *= inv; acc.y *= inv; acc.z *= inv; acc.w *= inv;

    reinterpret_cast<float4*>(out + (size_t)gb * DIM)[col] = acc;
}

extern "C" void kernel_launch(void* const* d_in, const int* in_sizes, int n_in,
                              void* d_out, int out_size)
{
    const float* h  = (const float*)d_in[0];
    const int*   op = (const int*)d_in[1];
    float*       o  = (float*)d_out;

    const int B = in_sizes[1] / NNODES;   // op_idx has B*N elements
    const int grid = (B + GPB - 1) / GPB;

    readout_kernel<<<grid, 256>>>(h, op, o, B);
}

// round 5
// speedup vs baseline: 1.1818x; 1.1818x over previous
#include <cuda_runtime.h>
#include <cstdint>

// Masked per-graph mean pooling.
// Inputs (metadata order):
//   d_in[0]: node_embeddings float32 [B*N, D] = [4096*64, 256]
//   d_in[1]: op_idx          int32   [B, N]   = [4096, 64]
// Output: float32 [B, D] = [4096, 256]
//
// out[b, :] = sum_{n: op[b,n]!=5} h[b,n,:] / max(count, 1)
//
// Shape (proven R2 geometry): one CTA per graph, 256 threads.
//   g   = tid>>6 : row group (0..3), 16 rows each
//   col = tid&63 : float4 column
// Streaming loads (__ldcs, zero reuse) + streaming stores (__stcs).

#define SKIP_OP 5
#define NNODES  64
#define DIM     256
#define DIM4    (DIM / 4)   // 64 float4 per row

__global__ __launch_bounds__(256, 8)
void readout_kernel(const float* __restrict__ h,
                    const int* __restrict__ op,
                    float* __restrict__ out)
{
    const int b   = blockIdx.x;
    const int tid = threadIdx.x;

    __shared__ float  mask[NNODES];
    __shared__ float4 partial[4][DIM4];
    __shared__ int    wcnt[2];

    // Stage the per-node mask; count via warp ballot (warps 0 and 1 cover 64 nodes).
    if (tid < NNODES) {
        const bool keep = (op[(size_t)b * NNODES + tid] != SKIP_OP);
        mask[tid] = keep ? 1.0f : 0.0f;
        const unsigned bal = __ballot_sync(0xffffffffu, keep);
        if ((tid & 31) == 0) wcnt[tid >> 5] = __popc(bal);
    }
    __syncthreads();

    const int col = tid & (DIM4 - 1);   // float4 column 0..63
    const int g   = tid >> 6;           // row group 0..3

    const float4* hp = reinterpret_cast<const float4*>(
        h + (size_t)b * NNODES * DIM);

    float4 acc = make_float4(0.f, 0.f, 0.f, 0.f);

    // 16 strided iterations; block touches 4 contiguous rows (4 KB) per step.
#pragma unroll
    for (int r = g; r < NNODES; r += 4) {
        const float  m = mask[r];
        const float4 v = __ldcs(&hp[r * DIM4 + col]);   // evict-first stream
        acc.x = fmaf(m, v.x, acc.x);
        acc.y = fmaf(m, v.y, acc.y);
        acc.z = fmaf(m, v.z, acc.z);
        acc.w = fmaf(m, v.w, acc.w);
    }

    partial[g][col] = acc;
    __syncthreads();

    if (tid < DIM4) {
        const float cnt = (float)(wcnt[0] + wcnt[1]);
        const float inv = 1.0f / fmaxf(cnt, 1.0f);

        float4 s0 = partial[0][tid];
        float4 s1 = partial[1][tid];
        float4 s2 = partial[2][tid];
        float4 s3 = partial[3][tid];
        float4 s;
        s.x = (s0.x + s1.x + s2.x + s3.x) * inv;
        s.y = (s0.y + s1.y + s2.y + s3.y) * inv;
        s.z = (s0.z + s1.z + s2.z + s3.z) * inv;
        s.w = (s0.w + s1.w + s2.w + s3.w) * inv;

        __stcs(&reinterpret_cast<float4*>(out + (size_t)b * DIM)[tid], s);
    }
}

extern "C" void kernel_launch(void* const* d_in, const int* in_sizes, int n_in,
                              void* d_out, int out_size)
{
    const float* h  = (const float*)d_in[0];
    const int*   op = (const int*)d_in[1];
    float*       o  = (float*)d_out;

    const int B = in_sizes[1] / NNODES;   // op_idx has B*N elements

    readout_kernel<<<B, 256>>>(h, op, o);
}